// round 8
// baseline (speedup 1.0000x reference)
#include <cuda_runtime.h>

// Problem shape (fixed by dataset instance)
#define B_   8
#define H_   96
#define W_   320
#define HWp  (H_ * W_)            // 30720
#define NPIX (B_ * HWp)           // 245760
#define VOL_ELEMS (B_ * 45 * HWp) // 11059200
#define INTERVAL (4.0f / 7.0f)
#define G_VOL  640                // persistent vol block slots (x3 iterations = 1920)
#define G_DISP 160                // persistent disp block slots (x3 iterations = 480)

// Bilinear sample, bank-column smem (slot i at win[i*128]).
// Unclamped: caller guarantees slots fi and fi+1 are written.
__device__ __forceinline__ float interp_u(const float* win, int fi, float w)
{
    float a = win[fi * 128];
    float b = win[(fi + 1) * 128];
    return __fmaf_rn(w, __fsub_rn(b, a), a);
}
// Clamped second tap (zero-weight overflow reads redirected into written slots).
__device__ __forceinline__ float interp_c(const float* win, int fi, int maxRel, float w)
{
    float a = win[fi * 128];
    float b = win[min(fi + 1, maxRel) * 128];
    return __fmaf_rn(w, __fsub_rn(b, a), a);
}

struct Px { float c0, c1, c2; int J2lo, n4, J1lo, idx; };

__device__ __forceinline__ Px mkpx(int idx, float d)
{
    Px q; q.idx = idx;
    float fx = (float)(idx % W_);
    q.c0 = fminf(fmaxf(__fsub_rn(fx, d), 0.0f), 319.0f);
    q.c1 = fminf(fmaxf(__fsub_rn(__fmul_rn(fx, 0.5f),  __fmul_rn(d, 0.5f)),  0.0f), 159.0f);
    q.c2 = fminf(fmaxf(__fsub_rn(__fmul_rn(fx, 0.25f), __fmul_rn(d, 0.25f)), 0.0f), 79.0f);
    q.J2lo = max(0, (int)floorf(q.c2) - 4);
    q.n4   = min(79, (int)ceilf(q.c2) + 4) - q.J2lo;
    q.J1lo = max(0, (int)floorf(q.c1) - 4);
    return q;
}

__global__ void __launch_bounds__(128, 7)
pcv_kernel(const float* __restrict__ corr,
           const float* __restrict__ disp,
           float* __restrict__ out)
{
    int bid = blockIdx.x;
    int t   = threadIdx.x;

    // ---- Disp-writer blocks (interleaved 1-in-5; persistent, 3 iterations) ----
    if (bid % 5 == 4) {
        int dp = bid / 5;                       // [0, G_DISP)
        #pragma unroll
        for (int k = 0; k < 3; ++k) {
            int g  = (dp + G_DISP * k) * 128 + t;   // quad index in [0, NPIX/4)
            int x4 = g % (W_ / 4);
            int bh = g / (W_ / 4);
            int x  = 4 * x4;
            float4 d4 = *reinterpret_cast<const float4*>(disp + bh * W_ + x);
            int b = bh / H_;
            int h = bh - b * H_;
            float* dst = out + VOL_ELEMS + ((size_t)(b * 45) * H_ + h) * W_ + x;
            #pragma unroll
            for (int lv = 0; lv < 3; ++lv) {
                float inv = (lv == 0) ? 1.0f : (lv == 1) ? 0.5f : 0.25f;
                float4 dl;
                dl.x = __fmul_rn(d4.x, inv); dl.y = __fmul_rn(d4.y, inv);
                dl.z = __fmul_rn(d4.z, inv); dl.w = __fmul_rn(d4.w, inv);
                #pragma unroll
                for (int c = 0; c < 15; ++c) {
                    float kk = __fmul_rn((float)(c - 7), INTERVAL);
                    float4 v;
                    v.x = __fadd_rn(kk, dl.x); v.y = __fadd_rn(kk, dl.y);
                    v.z = __fadd_rn(kk, dl.z); v.w = __fadd_rn(kk, dl.w);
                    *reinterpret_cast<float4*>(dst + (size_t)(lv * 15 + c) * HWp) = v;
                }
            }
        }
        return;
    }

    // ---- Vol blocks (persistent, software-pipelined over 3 pixels/thread) ----
    // Slot-major per-thread windows: element (slot, t) at [slot*128 + t].
    __shared__ float l0S[16 * 128];
    __shared__ float p1S[10 * 128];
    __shared__ float p2S[10 * 128];

    float* l0 = l0S + t;
    float* p1 = p1S + t;
    float* p2 = p2S + t;

    const float4* corr4 = reinterpret_cast<const float4*>(corr);

    int vbid = (bid / 5) * 4 + (bid % 5);       // [0, G_VOL)

    // Pipeline prologue: disp prefetched 2 deep, corr gather 1 deep.
    int idx0 = vbid * 128 + t;
    float d0 = __ldg(disp + idx0);
    float dn = __ldg(disp + idx0 + G_VOL * 128);   // disp for k=1
    Px cur = mkpx(idx0, d0);

    float4 vv[10];
    {
        const float4* r4 = corr4 + (size_t)idx0 * (W_ / 4);
        #pragma unroll
        for (int j = 0; j < 10; ++j)
            vv[j] = __ldcs(r4 + (cur.J2lo + min(j, cur.n4)));
    }

    #pragma unroll
    for (int k = 0; k < 3; ++k) {
        int K0 = max(0, (int)floorf(cur.c0) - 4) >> 2;   // recomputed (reg diet)

        // ---- Build windows for 'cur' from vv (consumes vv) ----
        #pragma unroll
        for (int jj = 0; jj < 10; ++jj) {
            float4 v = vv[jj];
            int q = cur.J2lo + jj - K0;
            if ((unsigned)q < 4u) {
                l0[(4*q+0) * 128] = v.x; l0[(4*q+1) * 128] = v.y;
                l0[(4*q+2) * 128] = v.z; l0[(4*q+3) * 128] = v.w;
            }
            float s0 = __fmul_rn(__fadd_rn(v.x, v.y), 0.5f);
            float s1 = __fmul_rn(__fadd_rn(v.z, v.w), 0.5f);
            int slot = 2 * (cur.J2lo + jj) - cur.J1lo;
            if ((unsigned)slot       < 10u) p1[slot * 128]       = s0;
            if ((unsigned)(slot + 1) < 10u) p1[(slot + 1) * 128] = s1;
            p2[jj * 128] = __fmul_rn(__fadd_rn(s0, s1), 0.5f);
        }

        // ---- Prefetch next pixel: gather flies during sampling ----
        Px nxt = cur;
        if (k < 2) {
            int idxn = cur.idx + G_VOL * 128;
            nxt = mkpx(idxn, dn);
            const float4* r4 = corr4 + (size_t)idxn * (W_ / 4);
            #pragma unroll
            for (int j = 0; j < 10; ++j)
                vv[j] = __ldcs(r4 + (nxt.J2lo + min(j, nxt.n4)));
            if (k < 1) dn = __ldg(disp + idxn + G_VOL * 128);
        }

        // ---- Sample 'cur' (LDS + STG) while next gather is in flight ----
        int x  = cur.idx % W_;
        int bh = cur.idx / W_;
        int b  = bh / H_;
        int h  = bh - b * H_;
        int volBase = (b * 45 * H_ + h) * W_ + x;
        float fx = (float)x;

        const float ctr[3]   = {cur.c0, cur.c1, cur.c2};
        const float w1m1a[3] = {319.0f, 159.0f, 79.0f};
        // Clamp for zero-weight +1 reads: l0 never needs one (all 16 slots written,
        // max access rel 13); p1 computed; p2 constant.
        const int maxRelA[3] = { 15,
                                 min(9, 2 * (cur.J2lo + cur.n4) + 1 - cur.J1lo),
                                 9 };

        #pragma unroll
        for (int lv = 0; lv < 3; ++lv) {
            const float* win = (lv == 0) ? l0 : (lv == 1) ? p1 : p2;
            int   base   = (lv == 0) ? 4 * K0 : (lv == 1) ? cur.J1lo : cur.J2lo;
            int   maxRel = maxRelA[lv];
            float inv    = (lv == 0) ? 1.0f : (lv == 1) ? 0.5f : 0.25f;
            float center = ctr[lv];
            float w1m1   = w1m1a[lv];
            float stdv   = __fmul_rn(fx, inv);
            float cm4 = __fsub_rn(center, 4.0f);
            float cp4 = __fadd_rn(center, 4.0f);

            float* outL = out + volBase + lv * 15 * HWp;

            #pragma unroll
            for (int s = 0; s < 8; ++s) {
                float off = __fmul_rn((float)s, INTERVAL);
                // left branch: guard implies 0 < lc <= w1m1, indices in-window
                float lc = __fadd_rn(cm4, off);
                float vl = 0.0f;
                if (lc > 0.0f) {
                    float f = floorf(lc);
                    vl = (lv == 0)
                       ? interp_u(win, (int)f - base, __fsub_rn(lc, f))
                       : interp_c(win, (int)f - base, maxRel, __fsub_rn(lc, f));
                }
                outL[s * HWp] = vl;
                // right branch: sample s -> channel 14-s (s=7 dup center dropped)
                if (s < 7) {
                    float rc = __fsub_rn(cp4, off);
                    float dnm = __fsub_rn(stdv, rc);
                    float vr = 0.0f;
                    if (dnm > 0.0f && dnm < w1m1) {
                        float cc = fminf(rc, w1m1);
                        float f  = floorf(cc);
                        vr = (lv == 0)
                           ? interp_u(win, (int)f - base, __fsub_rn(cc, f))
                           : interp_c(win, (int)f - base, maxRel, __fsub_rn(cc, f));
                    }
                    outL[(14 - s) * HWp] = vr;
                }
            }
        }

        cur = nxt;
    }
}

extern "C" void kernel_launch(void* const* d_in, const int* in_sizes, int n_in,
                              void* d_out, int out_size)
{
    const float* corr = (const float*)d_in[0];   // cross_attention [8,96,320,320]
    const float* disp = (const float*)d_in[1];   // cur_disp [8,1,96,320]
    float* out = (float*)d_out;                  // [vol ; disps], each [8,45,96,320]
    pcv_kernel<<<G_VOL + G_DISP, 128>>>(corr, disp, out);
}